// round 3
// baseline (speedup 1.0000x reference)
#include <cuda_runtime.h>

// GaussianPooling: out[n,c] = sum_{dy,dx} fm[c, y+dy, x+dx] * kern[dy,dx]
// fm: [512,256,256] f32, keypoints: [4096,2] int (x,y), out: [4096,512] f32.
// Separable 5x5 Gaussian (sigma=2).
//
// Strategy: block = (stripe of 64 rows, channel). Stage stripe (+2-row halo)
// into SMEM coalesced; service all keypoints in the stripe from SMEM.

#define C_DIM 512
#define H_DIM 256
#define W_DIM 256
#define N_KP  4096
#define PLANE (H_DIM * W_DIM)
#define STRIPE_ROWS 64
#define N_STRIPES (H_DIM / STRIPE_ROWS)          // 4
#define TILE_ROWS (STRIPE_ROWS + 4)              // 68 (2-row halo each side)
#define SM_STRIDE 260                            // 256 + 4 pad (bank spread)
#define TILE_FLOATS (TILE_ROWS * SM_STRIDE)      // 17680
#define TILE_BYTES (TILE_FLOATS * 4)             // 70720

__device__ int2 g_xy[N_KP];                      // clipped keypoint coords

static __device__ __forceinline__ float gval(float i) {
    float d = i - 2.0f;
    return __expf(-d * d * 0.125f);              // exp(-d^2/(2*2^2))
}

// Single block: detect keypoint dtype (int32 vs int64 pairs), then write
// clipped int2 coords to g_xy. int64 little-endian => odd int32 words are
// zero high-halves; int32 => odd words are y coords (nonzero somewhere).
__global__ void prep_kp_kernel(const int* __restrict__ kp32)
{
    __shared__ int s_or[256];
    __shared__ int s_flag;
    const int t = threadIdx.x;

    int acc = 0;
    for (int i = 1 + 2 * t; i < 2 * N_KP; i += 2 * 256) acc |= kp32[i];
    s_or[t] = acc;
    __syncthreads();
    for (int s = 128; s > 0; s >>= 1) {
        if (t < s) s_or[t] |= s_or[t + s];
        __syncthreads();
    }
    if (t == 0) s_flag = s_or[0];
    __syncthreads();
    const bool is_i32 = (s_flag != 0);

    for (int n = t; n < N_KP; n += 256) {
        int x, y;
        if (is_i32) { x = kp32[2 * n];     y = kp32[2 * n + 1]; }
        else        { x = kp32[4 * n];     y = kp32[4 * n + 2]; }
        x = min(max(x, 2), W_DIM - 3);
        y = min(max(y, 2), H_DIM - 3);
        g_xy[n] = make_int2(x, y);
    }
}

__global__ void __launch_bounds__(256)
gauss_pool_kernel(const float* __restrict__ fm, float* __restrict__ out)
{
    extern __shared__ float s_tile[];            // [TILE_ROWS][SM_STRIDE]
    __shared__ int   s_q[N_KP];                  // packed (n<<16)|(x<<8)|y
    __shared__ int   s_cnt;
    __shared__ float s_gx[4][8];                 // shifted horiz weights per off

    const int c      = blockIdx.x & (C_DIM - 1); // channel (fastest)
    const int stripe = blockIdx.x >> 9;
    const int t      = threadIdx.x;
    const int row0   = stripe * STRIPE_ROWS - 2;

    if (t == 0) s_cnt = 0;

    const float inv_norm =
        1.0f / (gval(0.f) + gval(1.f) + gval(2.f) + gval(3.f) + gval(4.f));

    if (t < 32) {
        int off = t >> 3, j = t & 7;
        int i = j - off;
        s_gx[off][j] = (i >= 0 && i < 5) ? gval((float)i) * inv_norm : 0.0f;
    }

    // ---- stage stripe into SMEM (coalesced float4 loads) ----
    const float* plane = fm + (size_t)c * PLANE;
    for (int idx = t; idx < TILE_ROWS * (W_DIM / 4); idx += 256) {
        int i    = idx >> 6;                     // tile row 0..67
        int col4 = idx & 63;                     // float4 column
        int gr   = min(max(row0 + i, 0), H_DIM - 1);
        float4 v = *(const float4*)(plane + gr * W_DIM + col4 * 4);
        *(float4*)&s_tile[i * SM_STRIDE + col4 * 4] = v;
    }
    __syncthreads();

    // ---- scan keypoints for this stripe ----
    for (int n = t; n < N_KP; n += 256) {
        int2 xy = g_xy[n];
        if ((xy.y >> 6) == stripe) {
            int idx = atomicAdd(&s_cnt, 1);
            s_q[idx] = (n << 16) | (xy.x << 8) | xy.y;
        }
    }
    __syncthreads();
    const int cnt = s_cnt;

    float gy[5];
    #pragma unroll
    for (int r = 0; r < 5; ++r) gy[r] = gval((float)r) * inv_norm;

    // ---- service keypoints from SMEM ----
    for (int q = t; q < cnt; q += 256) {
        const int v = s_q[q];
        const int y = v & 255;
        const int x = (v >> 8) & 255;
        const int n = v >> 16;

        const int w0  = x - 2;
        const int a   = w0 & ~3;
        const int off = w0 - a;

        float gx[8];
        #pragma unroll
        for (int j = 0; j < 8; ++j) gx[j] = s_gx[off][j];

        const int smrow = y - stripe * STRIPE_ROWS;   // (y-2) - row0
        const float* base = &s_tile[smrow * SM_STRIDE + a];

        float acc = 0.0f;
        #pragma unroll
        for (int r = 0; r < 5; ++r) {
            float4 A = *(const float4*)(base + r * SM_STRIDE);
            float4 B = *(const float4*)(base + r * SM_STRIDE + 4);
            float rs = gx[0] * A.x + gx[1] * A.y
                     + gx[2] * A.z + gx[3] * A.w
                     + gx[4] * B.x + gx[5] * B.y
                     + gx[6] * B.z + gx[7] * B.w;
            acc = fmaf(gy[r], rs, acc);
        }
        out[n * C_DIM + c] = acc;
    }
}

extern "C" void kernel_launch(void* const* d_in, const int* in_sizes, int n_in,
                              void* d_out, int out_size)
{
    const float* fm   = (const float*)d_in[0];
    const int*   kp32 = (const int*)d_in[1];
    float*       out  = (float*)d_out;

    cudaFuncSetAttribute(gauss_pool_kernel,
                         cudaFuncAttributeMaxDynamicSharedMemorySize,
                         TILE_BYTES);

    prep_kp_kernel<<<1, 256>>>(kp32);
    gauss_pool_kernel<<<N_STRIPES * C_DIM, 256, TILE_BYTES>>>(fm, out);
}

// round 4
// speedup vs baseline: 2.1090x; 2.1090x over previous
#include <cuda_runtime.h>

// GaussianPooling: out[n,c] = sum_{dy,dx} fm[c, y+dy, x+dx] * kern[dy,dx]
// fm: [512,256,256] f32, keypoints: [4096,2] int (x,y), out: [4096,512] f32.
// Separable 5x5 Gaussian (sigma=2).
//
// Strategy: prep kernel bins keypoints into 8 row-stripe queues (once).
// Main kernel: block = (stripe, channel); stage 36-row tile into SMEM
// coalesced, service the stripe's keypoints from SMEM.

#define C_DIM 512
#define H_DIM 256
#define W_DIM 256
#define N_KP  4096
#define PLANE (H_DIM * W_DIM)
#define STRIPE_ROWS 32
#define N_STRIPES (H_DIM / STRIPE_ROWS)          // 8
#define TILE_ROWS (STRIPE_ROWS + 4)              // 36
#define SM_STRIDE 260                            // 256 + 4 pad
#define TILE_FLOATS (TILE_ROWS * SM_STRIDE)      // 9360
#define TILE_BYTES (TILE_FLOATS * 4)             // 37440

__device__ int g_q[N_STRIPES * N_KP];            // packed (n<<16)|(x<<8)|y
__device__ int g_qcnt[N_STRIPES];

static __device__ __forceinline__ float gval(float i) {
    float d = i - 2.0f;
    return __expf(-d * d * 0.125f);              // exp(-d^2/(2*sigma^2))
}

// Single block: detect keypoint dtype (int32 vs int64 pairs), clip coords,
// bin into per-stripe queues. int64 LE => odd int32 words are zero highs.
__global__ void prep_kp_kernel(const int* __restrict__ kp32)
{
    __shared__ int s_or[256];
    __shared__ int s_flag;
    __shared__ int s_cnt[N_STRIPES];
    const int t = threadIdx.x;

    int acc = 0;
    for (int i = 1 + 2 * t; i < 2 * N_KP; i += 2 * 256) acc |= kp32[i];
    s_or[t] = acc;
    if (t < N_STRIPES) s_cnt[t] = 0;
    __syncthreads();
    for (int s = 128; s > 0; s >>= 1) {
        if (t < s) s_or[t] |= s_or[t + s];
        __syncthreads();
    }
    if (t == 0) s_flag = s_or[0];
    __syncthreads();
    const bool is_i32 = (s_flag != 0);

    for (int n = t; n < N_KP; n += 256) {
        int x, y;
        if (is_i32) { x = kp32[2 * n];     y = kp32[2 * n + 1]; }
        else        { x = kp32[4 * n];     y = kp32[4 * n + 2]; }
        x = min(max(x, 2), W_DIM - 3);
        y = min(max(y, 2), H_DIM - 3);
        int stripe = y / STRIPE_ROWS;
        int idx = atomicAdd(&s_cnt[stripe], 1);
        g_q[stripe * N_KP + idx] = (n << 16) | (x << 8) | y;
    }
    __syncthreads();
    if (t < N_STRIPES) g_qcnt[t] = s_cnt[t];
}

__global__ void __launch_bounds__(256)
gauss_pool_kernel(const float* __restrict__ fm, float* __restrict__ out)
{
    extern __shared__ float s_tile[];            // [TILE_ROWS][SM_STRIDE]
    __shared__ float s_gx[4][8];

    const int c      = blockIdx.x & (C_DIM - 1);
    const int stripe = blockIdx.x >> 9;
    const int t      = threadIdx.x;
    const int row0   = stripe * STRIPE_ROWS - 2;

    const float inv_norm =
        1.0f / (gval(0.f) + gval(1.f) + gval(2.f) + gval(3.f) + gval(4.f));

    if (t < 32) {
        int off = t >> 3, j = t & 7;
        int i = j - off;
        s_gx[off][j] = (i >= 0 && i < 5) ? gval((float)i) * inv_norm : 0.0f;
    }

    // ---- stage stripe (+halo) into SMEM, coalesced float4 ----
    const float* plane = fm + (size_t)c * PLANE;
    #pragma unroll
    for (int idx = 0; idx < TILE_ROWS * (W_DIM / 4); idx += 256) {
        int k    = idx + t;
        int i    = k >> 6;                       // tile row 0..35
        int col4 = k & 63;
        int gr   = min(max(row0 + i, 0), H_DIM - 1);
        float4 v = *(const float4*)(plane + gr * W_DIM + col4 * 4);
        *(float4*)&s_tile[i * SM_STRIDE + col4 * 4] = v;
    }
    __syncthreads();

    const int cnt = g_qcnt[stripe];
    const int* q  = &g_q[stripe * N_KP];

    float gy[5];
    #pragma unroll
    for (int r = 0; r < 5; ++r) gy[r] = gval((float)r) * inv_norm;

    // ---- service keypoints from SMEM ----
    for (int i = t; i < cnt; i += 256) {
        const int v = q[i];                      // coalesced, L2-hot
        const int y = v & 255;
        const int x = (v >> 8) & 255;
        const int n = v >> 16;

        const int w0  = x - 2;
        const int a   = w0 & ~3;
        const int off = w0 - a;

        float gx[8];
        #pragma unroll
        for (int j = 0; j < 8; ++j) gx[j] = s_gx[off][j];

        const int smrow = y - stripe * STRIPE_ROWS;   // (y-2) - row0
        const float* base = &s_tile[smrow * SM_STRIDE + a];

        float acc = 0.0f;
        #pragma unroll
        for (int r = 0; r < 5; ++r) {
            float4 A = *(const float4*)(base + r * SM_STRIDE);
            float4 B = *(const float4*)(base + r * SM_STRIDE + 4);
            float rs = gx[0] * A.x + gx[1] * A.y
                     + gx[2] * A.z + gx[3] * A.w
                     + gx[4] * B.x + gx[5] * B.y
                     + gx[6] * B.z + gx[7] * B.w;
            acc = fmaf(gy[r], rs, acc);
        }
        out[n * C_DIM + c] = acc;
    }
}

extern "C" void kernel_launch(void* const* d_in, const int* in_sizes, int n_in,
                              void* d_out, int out_size)
{
    const float* fm   = (const float*)d_in[0];
    const int*   kp32 = (const int*)d_in[1];
    float*       out  = (float*)d_out;

    cudaFuncSetAttribute(gauss_pool_kernel,
                         cudaFuncAttributeMaxDynamicSharedMemorySize,
                         TILE_BYTES);

    prep_kp_kernel<<<1, 256>>>(kp32);
    gauss_pool_kernel<<<N_STRIPES * C_DIM, 256, TILE_BYTES>>>(fm, out);
}

// round 5
// speedup vs baseline: 2.4090x; 1.1422x over previous
#include <cuda_runtime.h>

// GaussianPooling: out[n,c] = sum_{dy,dx} fm[c, y+dy, x+dx] * kern[dy,dx]
// fm: [512,256,256] f32, keypoints: [4096,2] int (x,y), out: [4096,512] f32.
// Separable 5x5 Gaussian (sigma=2): kern = outer(g,g), g normalized.
//
// Main kernel: block = (stripe of 32 rows, channel).
//   Phase 1: vertical 5-tap conv from GLOBAL directly into SMEM tile V
//            (register rolling window, coalesced float4 loads).
//   Phase 2: per keypoint, horizontal dot over ONE row of V: 2x LDS.128.

#define C_DIM 512
#define H_DIM 256
#define W_DIM 256
#define N_KP  4096
#define PLANE (H_DIM * W_DIM)
#define STRIPE_ROWS 32
#define N_STRIPES (H_DIM / STRIPE_ROWS)          // 8
#define SM_STRIDE 260                            // 256 + 4 pad
#define V_FLOATS (STRIPE_ROWS * SM_STRIDE)       // 8320
#define V_BYTES (V_FLOATS * 4)                   // 33280

__device__ int g_q[N_STRIPES * N_KP];            // packed (n<<16)|(x<<8)|y
__device__ int g_qcnt[N_STRIPES];

static __device__ __forceinline__ float gval(float i) {
    float d = i - 2.0f;
    return __expf(-d * d * 0.125f);              // exp(-d^2/(2*sigma^2))
}

// 8 blocks, one per stripe: detect kp dtype, clip, compact this stripe's
// keypoints into its queue (smem atomics only; count OVERWRITTEN each launch).
__global__ void prep_kp_kernel(const int* __restrict__ kp32)
{
    __shared__ int s_or[256];
    __shared__ int s_flag;
    __shared__ int s_cnt;
    const int t      = threadIdx.x;
    const int stripe = blockIdx.x;

    int acc = 0;
    for (int i = 1 + 2 * t; i < 2 * N_KP; i += 2 * 256) acc |= kp32[i];
    s_or[t] = acc;
    if (t == 0) s_cnt = 0;
    __syncthreads();
    for (int s = 128; s > 0; s >>= 1) {
        if (t < s) s_or[t] |= s_or[t + s];
        __syncthreads();
    }
    if (t == 0) s_flag = s_or[0];
    __syncthreads();
    const bool is_i32 = (s_flag != 0);   // int64 LE: odd int32 words all zero

    for (int n = t; n < N_KP; n += 256) {
        int x, y;
        if (is_i32) { x = kp32[2 * n];     y = kp32[2 * n + 1]; }
        else        { x = kp32[4 * n];     y = kp32[4 * n + 2]; }
        x = min(max(x, 2), W_DIM - 3);
        y = min(max(y, 2), H_DIM - 3);
        if (y / STRIPE_ROWS == stripe) {
            int idx = atomicAdd(&s_cnt, 1);
            g_q[stripe * N_KP + idx] = (n << 16) | (x << 8) | y;
        }
    }
    __syncthreads();
    if (t == 0) g_qcnt[stripe] = s_cnt;
}

__global__ void __launch_bounds__(256)
gauss_pool_kernel(const float* __restrict__ fm, float* __restrict__ out)
{
    extern __shared__ float s_v[];               // V: [32][SM_STRIDE]
    __shared__ float s_gx[4][8];

    const int c      = blockIdx.x & (C_DIM - 1);
    const int stripe = blockIdx.x >> 9;
    const int t      = threadIdx.x;
    const int row0   = stripe * STRIPE_ROWS - 2; // first fm row needed

    const float inv_norm =
        1.0f / (gval(0.f) + gval(1.f) + gval(2.f) + gval(3.f) + gval(4.f));

    if (t < 32) {
        int off = t >> 3, j = t & 7;
        int i = j - off;
        s_gx[off][j] = (i >= 0 && i < 5) ? gval((float)i) * inv_norm : 0.0f;
    }

    const float g0 = gval(0.f) * inv_norm;       // == g4
    const float g1 = gval(1.f) * inv_norm;       // == g3
    const float g2 = gval(2.f) * inv_norm;

    // ---- Phase 1: vertical conv, global -> SMEM ----
    // thread = (chunk, strip): strip = t & 63 (fast, coalesced float4 cols),
    // chunk = t >> 6 covers 8 output rows, reads 12 input rows.
    {
        const int strip = t & 63;
        const int chunk = t >> 6;
        const float4* pl4 = (const float4*)(fm + (size_t)c * PLANE) + strip;

        float4 w0, w1, w2, w3, w4;
        const int L0 = chunk * 8;
        #pragma unroll
        for (int k = 0; k < 12; ++k) {
            const int li = L0 + k;
            const int gr = min(max(row0 + li, 0), H_DIM - 1);
            float4 v = pl4[gr * (W_DIM / 4)];
            w0 = w1; w1 = w2; w2 = w3; w3 = w4; w4 = v;
            if (k >= 4) {
                const int vi = li - 4;           // output V row
                float4 r;
                r.x = g0 * (w0.x + w4.x) + g1 * (w1.x + w3.x) + g2 * w2.x;
                r.y = g0 * (w0.y + w4.y) + g1 * (w1.y + w3.y) + g2 * w2.y;
                r.z = g0 * (w0.z + w4.z) + g1 * (w1.z + w3.z) + g2 * w2.z;
                r.w = g0 * (w0.w + w4.w) + g1 * (w1.w + w3.w) + g2 * w2.w;
                *(float4*)&s_v[vi * SM_STRIDE + strip * 4] = r;
            }
        }
    }
    __syncthreads();

    // ---- Phase 2: per-keypoint horizontal dot on one V row ----
    const int cnt = g_qcnt[stripe];
    const int* q  = &g_q[stripe * N_KP];

    for (int i = t; i < cnt; i += 256) {
        const int v = q[i];
        const int y = v & 255;
        const int x = (v >> 8) & 255;
        const int n = v >> 16;

        const int w0c = x - 2;
        const int a   = w0c & ~3;
        const int off = w0c - a;
        const int yl  = y - stripe * STRIPE_ROWS;

        const float* base = &s_v[yl * SM_STRIDE + a];
        float4 A = *(const float4*)(base);
        float4 B = *(const float4*)(base + 4);

        const float* gx = s_gx[off];
        float acc = gx[0] * A.x + gx[1] * A.y + gx[2] * A.z + gx[3] * A.w
                  + gx[4] * B.x + gx[5] * B.y + gx[6] * B.z + gx[7] * B.w;

        out[n * C_DIM + c] = acc;
    }
}

extern "C" void kernel_launch(void* const* d_in, const int* in_sizes, int n_in,
                              void* d_out, int out_size)
{
    const float* fm   = (const float*)d_in[0];
    const int*   kp32 = (const int*)d_in[1];
    float*       out  = (float*)d_out;

    cudaFuncSetAttribute(gauss_pool_kernel,
                         cudaFuncAttributeMaxDynamicSharedMemorySize,
                         V_BYTES);

    prep_kp_kernel<<<N_STRIPES, 256>>>(kp32);
    gauss_pool_kernel<<<N_STRIPES * C_DIM, 256, V_BYTES>>>(fm, out);
}

// round 6
// speedup vs baseline: 2.5911x; 1.0756x over previous
#include <cuda_runtime.h>

// GaussianPooling: out[n,c] = sum_{dy,dx} fm[c, y+dy, x+dx] * kern[dy,dx]
// fm: [512,256,256] f32, keypoints: [4096,2] int (x,y), out: [4096,512] f32.
// Separable 5x5 Gaussian (sigma=2).
//
// prep: bin keypoints into 8 row-stripe queues.
// main: block = (stripe, pair of channels). Vertical conv global->SMEM,
//       then per keypoint one horizontal dot per channel; STG.64 output.
//       Launched with PDL so it overlaps the prep launch.

#define C_DIM 512
#define H_DIM 256
#define W_DIM 256
#define N_KP  4096
#define PLANE (H_DIM * W_DIM)
#define STRIPE_ROWS 32
#define N_STRIPES (H_DIM / STRIPE_ROWS)          // 8
#define SM_STRIDE 260                            // 256 + 4 pad
#define V_FLOATS (STRIPE_ROWS * SM_STRIDE)       // 8320 floats per channel tile
#define CG 2                                     // channels per block
#define SMEM_BYTES (CG * V_FLOATS * 4)           // 66560

__device__ int g_q[N_STRIPES * N_KP];            // packed (n<<16)|(x<<8)|y
__device__ int g_qcnt[N_STRIPES];

static __device__ __forceinline__ float gval(float i) {
    float d = i - 2.0f;
    return __expf(-d * d * 0.125f);              // exp(-d^2/(2*sigma^2))
}

// 8 blocks, one per stripe: detect kp dtype (int64 LE => odd int32 words all
// zero), clip, compact this stripe's keypoints into its queue.
__global__ void prep_kp_kernel(const int* __restrict__ kp32)
{
    __shared__ int s_or[256];
    __shared__ int s_flag;
    __shared__ int s_cnt;
    const int t      = threadIdx.x;
    const int stripe = blockIdx.x;

    int acc = 0;
    for (int i = 1 + 2 * t; i < 2 * N_KP; i += 2 * 256) acc |= kp32[i];
    s_or[t] = acc;
    if (t == 0) s_cnt = 0;
    __syncthreads();
    for (int s = 128; s > 0; s >>= 1) {
        if (t < s) s_or[t] |= s_or[t + s];
        __syncthreads();
    }
    if (t == 0) s_flag = s_or[0];
    __syncthreads();
    const bool is_i32 = (s_flag != 0);

    for (int n = t; n < N_KP; n += 256) {
        int x, y;
        if (is_i32) { x = kp32[2 * n];     y = kp32[2 * n + 1]; }
        else        { x = kp32[4 * n];     y = kp32[4 * n + 2]; }
        x = min(max(x, 2), W_DIM - 3);
        y = min(max(y, 2), H_DIM - 3);
        if (y / STRIPE_ROWS == stripe) {
            int idx = atomicAdd(&s_cnt, 1);
            g_q[stripe * N_KP + idx] = (n << 16) | (x << 8) | y;
        }
    }
    __syncthreads();
    if (t == 0) g_qcnt[stripe] = s_cnt;
}

__global__ void __launch_bounds__(256)
gauss_pool_kernel(const float* __restrict__ fm, float* __restrict__ out)
{
    extern __shared__ float s_v[];               // CG tiles of [32][SM_STRIDE]
    __shared__ float s_gx[4][8];

    const int cg0    = (blockIdx.x & 255) * CG;  // first channel of pair
    const int stripe = blockIdx.x >> 8;
    const int t      = threadIdx.x;
    const int row0   = stripe * STRIPE_ROWS - 2;

    const float inv_norm =
        1.0f / (gval(0.f) + gval(1.f) + gval(2.f) + gval(3.f) + gval(4.f));

    if (t < 32) {
        int off = t >> 3, j = t & 7;
        int i = j - off;
        s_gx[off][j] = (i >= 0 && i < 5) ? gval((float)i) * inv_norm : 0.0f;
    }

    const float g0 = gval(0.f) * inv_norm;
    const float g1 = gval(1.f) * inv_norm;
    const float g2 = gval(2.f) * inv_norm;

    // ---- Phase 1: vertical conv, global -> SMEM, per channel ----
    // thread = (chunk = t>>6 covering 8 V-rows, strip = t&63 float4 column)
    const int strip = t & 63;
    const int chunk = t >> 6;
    const int L0    = chunk * 8;

    #pragma unroll
    for (int cg = 0; cg < CG; ++cg) {
        const float4* pl4 =
            (const float4*)(fm + (size_t)(cg0 + cg) * PLANE) + strip;
        float* tile = s_v + cg * V_FLOATS;

        float4 w0, w1, w2, w3, w4;
        #pragma unroll
        for (int k = 0; k < 12; ++k) {
            const int li = L0 + k;
            const int gr = min(max(row0 + li, 0), H_DIM - 1);
            float4 v = pl4[gr * (W_DIM / 4)];
            w0 = w1; w1 = w2; w2 = w3; w3 = w4; w4 = v;
            if (k >= 4) {
                float4 r;
                r.x = g0 * (w0.x + w4.x) + g1 * (w1.x + w3.x) + g2 * w2.x;
                r.y = g0 * (w0.y + w4.y) + g1 * (w1.y + w3.y) + g2 * w2.y;
                r.z = g0 * (w0.z + w4.z) + g1 * (w1.z + w3.z) + g2 * w2.z;
                r.w = g0 * (w0.w + w4.w) + g1 * (w1.w + w3.w) + g2 * w2.w;
                *(float4*)&tile[(li - 4) * SM_STRIDE + strip * 4] = r;
            }
        }
    }

    // queues are produced by prep_kp_kernel (PDL-ordered)
    cudaGridDependencySynchronize();
    __syncthreads();

    // ---- Phase 2: per-keypoint horizontal dot, one row per channel ----
    const int cnt = g_qcnt[stripe];
    const int* q  = &g_q[stripe * N_KP];

    for (int i = t; i < cnt; i += 256) {
        const int v = q[i];
        const int y = v & 255;
        const int x = (v >> 8) & 255;
        const int n = v >> 16;

        const int w0c = x - 2;
        const int a   = w0c & ~3;
        const int off = w0c - a;
        const int yl  = y - stripe * STRIPE_ROWS;
        const float* gx = s_gx[off];

        float2 res;
        #pragma unroll
        for (int cg = 0; cg < CG; ++cg) {
            const float* base = s_v + cg * V_FLOATS + yl * SM_STRIDE + a;
            float4 A = *(const float4*)(base);
            float4 B = *(const float4*)(base + 4);
            float r = gx[0] * A.x + gx[1] * A.y + gx[2] * A.z + gx[3] * A.w
                    + gx[4] * B.x + gx[5] * B.y + gx[6] * B.z + gx[7] * B.w;
            if (cg == 0) res.x = r; else res.y = r;
        }
        *(float2*)&out[n * C_DIM + cg0] = res;
    }
}

extern "C" void kernel_launch(void* const* d_in, const int* in_sizes, int n_in,
                              void* d_out, int out_size)
{
    const float* fm   = (const float*)d_in[0];
    const int*   kp32 = (const int*)d_in[1];
    float*       out  = (float*)d_out;

    cudaFuncSetAttribute(gauss_pool_kernel,
                         cudaFuncAttributeMaxDynamicSharedMemorySize,
                         SMEM_BYTES);

    prep_kp_kernel<<<N_STRIPES, 256>>>(kp32);

    // PDL: main kernel launch overlaps prep; gridDependencySynchronize
    // inside the kernel orders the queue reads.
    cudaLaunchConfig_t cfg = {};
    cfg.gridDim  = dim3(N_STRIPES * (C_DIM / CG));
    cfg.blockDim = dim3(256);
    cfg.dynamicSmemBytes = SMEM_BYTES;
    cfg.stream = 0;
    cudaLaunchAttribute attr[1];
    attr[0].id = cudaLaunchAttributeProgrammaticStreamSerialization;
    attr[0].val.programmaticStreamSerializationAllowed = 1;
    cfg.attrs = attr;
    cfg.numAttrs = 1;
    cudaLaunchKernelEx(&cfg, gauss_pool_kernel, fm, out);
}